// round 5
// baseline (speedup 1.0000x reference)
#include <cuda_runtime.h>
#include <cuda_fp16.h>

#define IN_SIZE   1024
#define IN_DIM    128
#define OUT_SIZE  64
#define MAX_ITERS 100

// shared memory byte offsets
#define SM_MT 0                         // 65536 halves (128KB), quad-interleaved:
                                        //  (o,s) -> Mt[(o>>2)*4096 + s*4 + (o&3)]
#define SM_XS 131072                    // GEMM: [128][132] f32 padded (67584B)
                                        // epilogue: 2x 64-row chunks (64KB) then partials
#define SM_RV 198656                    // 1024 f32
#define SM_CV 202752                    // 64 f32
#define SM_PT 203008                    // 128 f32 partials (512B)
#define SM_FL 203520                    // 2 ints
#define SM_TOTAL 203584

typedef unsigned long long u64;

__device__ __forceinline__ void ffma2(u64& d, u64 a, u64 b) {
    asm("fma.rn.f32x2 %0, %1, %2, %0;" : "+l"(d) : "l"(a), "l"(b));
}
__device__ __forceinline__ u64 dupf(float x) {
    u64 r; asm("mov.b64 %0, {%1, %1};" : "=l"(r) : "f"(x)); return r;
}
__device__ __forceinline__ float pairsum(u64 p) {
    float lo, hi; asm("mov.b64 {%0, %1}, %2;" : "=f"(lo), "=f"(hi) : "l"(p));
    return lo + hi;
}
__device__ __forceinline__ float2 pair2f(u64 p) {
    float2 f; asm("mov.b64 {%0, %1}, %2;" : "=f"(f.x), "=f"(f.y) : "l"(p));
    return f;
}

__global__ __launch_bounds__(1024, 1) void ot_fused_kernel(
    const float* __restrict__ x, const float* __restrict__ w,
    float* __restrict__ out)
{
    extern __shared__ char sm[];
    __half* Mt    = (__half*)(sm + SM_MT);
    float*  xs    = (float*)(sm + SM_XS);
    float*  rv    = (float*)(sm + SM_RV);
    float*  cv    = (float*)(sm + SM_CV);
    float*  part  = (float*)(sm + SM_PT);
    int*    flags = (int*)(sm + SM_FL);

    const int b = blockIdx.x;
    const int n = b >> 2, m = b & 3;
    const int t = threadIdx.x;
    const int lane = t & 31, wp = t >> 5;
    const int og = t >> 6;              // 0..15  (o-quad)
    const int sl = t & 63;

    const float* xb = x + (size_t)n * IN_SIZE * IN_DIM;
    const float* wq = w + ((size_t)m * OUT_SIZE + og * 4) * IN_DIM;

    if (t == 0) { flags[0] = 0; flags[1] = 0; }
    if (t < 64) cv[t] = 1.0f;

    // ------------------------------------------------------------------
    // Phase 1: K[s,o] = x[s,:]·w[o,:];  Mt = exp(K)  (fp16, in smem)
    // FFMA2 (f32x2) paired over k: operands are natural b64 register pairs.
    // ------------------------------------------------------------------
    for (int pr = 0; pr < 8; ++pr) {
        __syncthreads();
        const float4* xg = (const float4*)(xb + pr * 128 * IN_DIM);
#pragma unroll
        for (int jj = 0; jj < 4; ++jj) {
            int idx = jj * 1024 + t;              // 4096 float4 per pass
            float4 v = xg[idx];
            int row = idx >> 5, kq = idx & 31;
            *(float4*)(xs + row * 132 + kq * 4) = v;   // padded: conflict-free
        }
        __syncthreads();

        u64 pA0 = 0, pA1 = 0, pA2 = 0, pA3 = 0;
        u64 pB0 = 0, pB1 = 0, pB2 = 0, pB3 = 0;
#pragma unroll 2
        for (int kc = 0; kc < 32; ++kc) {
            float4 xA = *(const float4*)(xs + sl        * 132 + kc * 4);
            float4 xB = *(const float4*)(xs + (sl + 64) * 132 + kc * 4);
            float4 w0 = *(const float4*)(wq + 0 * IN_DIM + kc * 4);
            float4 w1 = *(const float4*)(wq + 1 * IN_DIM + kc * 4);
            float4 w2 = *(const float4*)(wq + 2 * IN_DIM + kc * 4);
            float4 w3 = *(const float4*)(wq + 3 * IN_DIM + kc * 4);
            u64 xa0 = ((u64*)&xA)[0], xa1 = ((u64*)&xA)[1];
            u64 xb0 = ((u64*)&xB)[0], xb1 = ((u64*)&xB)[1];
            u64 w0l = ((u64*)&w0)[0], w0h = ((u64*)&w0)[1];
            u64 w1l = ((u64*)&w1)[0], w1h = ((u64*)&w1)[1];
            u64 w2l = ((u64*)&w2)[0], w2h = ((u64*)&w2)[1];
            u64 w3l = ((u64*)&w3)[0], w3h = ((u64*)&w3)[1];
            ffma2(pA0, xa0, w0l); ffma2(pA0, xa1, w0h);
            ffma2(pA1, xa0, w1l); ffma2(pA1, xa1, w1h);
            ffma2(pA2, xa0, w2l); ffma2(pA2, xa1, w2h);
            ffma2(pA3, xa0, w3l); ffma2(pA3, xa1, w3h);
            ffma2(pB0, xb0, w0l); ffma2(pB0, xb1, w0h);
            ffma2(pB1, xb0, w1l); ffma2(pB1, xb1, w1h);
            ffma2(pB2, xb0, w2l); ffma2(pB2, xb1, w2h);
            ffma2(pB3, xb0, w3l); ffma2(pB3, xb1, w3h);
        }
        const int S0 = pr * 128 + sl, S1 = S0 + 64;
        {
            __half2 h0 = __floats2half2_rn(__expf(pairsum(pA0)), __expf(pairsum(pA1)));
            __half2 h1 = __floats2half2_rn(__expf(pairsum(pA2)), __expf(pairsum(pA3)));
            uint2 pk; pk.x = *(unsigned*)&h0; pk.y = *(unsigned*)&h1;
            *(uint2*)(Mt + og * 4096 + S0 * 4) = pk;
        }
        {
            __half2 h0 = __floats2half2_rn(__expf(pairsum(pB0)), __expf(pairsum(pB1)));
            __half2 h1 = __floats2half2_rn(__expf(pairsum(pB2)), __expf(pairsum(pB3)));
            uint2 pk; pk.x = *(unsigned*)&h0; pk.y = *(unsigned*)&h1;
            *(uint2*)(Mt + og * 4096 + S1 * 4) = pk;
        }
    }
    __syncthreads();

    // ------------------------------------------------------------------
    // Phase 2: multiplicative Sinkhorn.  r_s = (1/16)/Σ_o M c ; c_o = 1/Σ_s M r
    // u-pass: thread t = row t.  v-pass: warp (q=wp&15, h=wp>>4) owns o-quad q
    // over row-half h (conflict-free LDS.64).  Early exit on converged c.
    // ------------------------------------------------------------------
    const float A = 1.0f / 16.0f;
    const int vq = wp & 15, vh = wp >> 4;
    float r = 0.f;

    for (int it = 0; it < MAX_ITERS; ++it) {
        // u-pass
        float dot = 0.f;
#pragma unroll
        for (int qq = 0; qq < 16; ++qq) {
            uint2 mm  = *(const uint2*)(Mt + qq * 4096 + t * 4);
            float4 cc = *(const float4*)(cv + qq * 4);
            float2 f0 = __half22float2(*(__half2*)&mm.x);
            float2 f1 = __half22float2(*(__half2*)&mm.y);
            dot += f0.x*cc.x + f0.y*cc.y + f1.x*cc.z + f1.y*cc.w;
        }
        r = __fdividef(A, dot);
        rv[t] = r;
        if (t == 0) flags[(it + 1) & 1] = 0;   // pre-clear next iter's flag
        __syncthreads();

        // v-pass: quad column sums over 512 rows per warp
        float s0 = 0.f, s1 = 0.f, s2 = 0.f, s3 = 0.f;
#pragma unroll 4
        for (int i = 0; i < 16; ++i) {
            const int s = vh * 512 + i * 32 + lane;
            uint2 mm = *(const uint2*)(Mt + vq * 4096 + s * 4);
            const float rr = rv[s];
            float2 f0 = __half22float2(*(__half2*)&mm.x);
            float2 f1 = __half22float2(*(__half2*)&mm.y);
            s0 += f0.x * rr; s1 += f0.y * rr; s2 += f1.x * rr; s3 += f1.y * rr;
        }
#pragma unroll
        for (int off = 16; off; off >>= 1) {
            s0 += __shfl_xor_sync(0xffffffffu, s0, off);
            s1 += __shfl_xor_sync(0xffffffffu, s1, off);
            s2 += __shfl_xor_sync(0xffffffffu, s2, off);
            s3 += __shfl_xor_sync(0xffffffffu, s3, off);
        }
        if (lane == 0) {
            float* p = part + (vq * 2 + vh) * 4;
            p[0] = s0; p[1] = s1; p[2] = s2; p[3] = s3;
        }
        __syncthreads();
        if (t < 64) {
            const int qn = t >> 2, j = t & 3;
            const float c = __fdividef(1.0f, part[qn * 8 + j] + part[qn * 8 + 4 + j]);
            const float o = cv[t];
            cv[t] = c;
            if (fabsf(c - o) > 1e-5f * fabsf(o)) flags[it & 1] = 1;
        }
        __syncthreads();
        if (it >= 2 && flags[it & 1] == 0) break;
    }

    // ------------------------------------------------------------------
    // Phase 3: fold r, c into Mt  ->  Mt holds T = diag(r) M diag(c)
    // ------------------------------------------------------------------
#pragma unroll
    for (int qq = 0; qq < 16; ++qq) {
        uint2 mm  = *(const uint2*)(Mt + qq * 4096 + t * 4);
        float4 cc = *(const float4*)(cv + qq * 4);
        float2 f0 = __half22float2(*(__half2*)&mm.x);
        float2 f1 = __half22float2(*(__half2*)&mm.y);
        __half2 g0 = __floats2half2_rn(f0.x * r * cc.x, f0.y * r * cc.y);
        __half2 g1 = __floats2half2_rn(f1.x * r * cc.z, f1.y * r * cc.w);
        uint2 pk; pk.x = *(unsigned*)&g0; pk.y = *(unsigned*)&g1;
        *(uint2*)(Mt + qq * 4096 + t * 4) = pk;
    }

    // ------------------------------------------------------------------
    // Phase 4: out[n, o, m*128+d] = Σ_s T[s,o] x[s,d]
    // 2-way s-split: sh = t>>9; thread tile = 4 o (quad eog) x 4 d (dq*4),
    // FFMA2 over d-pairs; partials combined through smem at the end.
    // ------------------------------------------------------------------
    const int sh  = t >> 9;
    const int rem = t & 511;
    const int eog = rem >> 5;            // o-quad, constant per warp
    const int dq  = t & 31;              // d = dq*4
    u64 acc[4][2];
#pragma unroll
    for (int oo = 0; oo < 4; ++oo) { acc[oo][0] = 0; acc[oo][1] = 0; }

    for (int cp = 0; cp < 8; ++cp) {
        __syncthreads();
        // stage chunk cp (rows cp*64..) and chunk cp+8 (rows 512+cp*64..)
        const float4* xg0 = (const float4*)(xb + (cp * 64) * IN_DIM);
        const float4* xg1 = (const float4*)(xb + (512 + cp * 64) * IN_DIM);
        float4* xs4 = (float4*)xs;
        xs4[t]            = xg0[t];
        xs4[t + 1024]     = xg0[t + 1024];
        xs4[2048 + t]        = xg1[t];
        xs4[2048 + t + 1024] = xg1[t + 1024];
        __syncthreads();
        const float* xsh = xs + sh * 8192;
        const int Sb = sh * 512 + cp * 64;
#pragma unroll 4
        for (int s = 0; s < 64; ++s) {
            const int S = Sb + s;
            uint2 mm = *(const uint2*)(Mt + eog * 4096 + S * 4);   // broadcast
            float4 xv = *(const float4*)(xsh + s * IN_DIM + dq * 4);
            u64 xlo = ((u64*)&xv)[0], xhi = ((u64*)&xv)[1];
            float2 f0 = __half22float2(*(__half2*)&mm.x);
            float2 f1 = __half22float2(*(__half2*)&mm.y);
            u64 t0 = dupf(f0.x), t1 = dupf(f0.y);
            u64 t2 = dupf(f1.x), t3 = dupf(f1.y);
            ffma2(acc[0][0], t0, xlo); ffma2(acc[0][1], t0, xhi);
            ffma2(acc[1][0], t1, xlo); ffma2(acc[1][1], t1, xhi);
            ffma2(acc[2][0], t2, xlo); ffma2(acc[2][1], t2, xhi);
            ffma2(acc[3][0], t3, xlo); ffma2(acc[3][1], t3, xhi);
        }
    }

    // combine the two s-halves through smem
    __syncthreads();
    {
        float2* dst = (float2*)(xs + sh * 8192 + rem * 16);
#pragma unroll
        for (int oo = 0; oo < 4; ++oo) {
            dst[oo * 2]     = pair2f(acc[oo][0]);
            dst[oo * 2 + 1] = pair2f(acc[oo][1]);
        }
    }
    __syncthreads();
    if (t < 512) {
        const float* p0 = xs + t * 16;
        const float* p1 = xs + 8192 + t * 16;
#pragma unroll
        for (int oo = 0; oo < 4; ++oo) {
            float4 res;
            res.x = p0[oo * 4 + 0] + p1[oo * 4 + 0];
            res.y = p0[oo * 4 + 1] + p1[oo * 4 + 1];
            res.z = p0[oo * 4 + 2] + p1[oo * 4 + 2];
            res.w = p0[oo * 4 + 3] + p1[oo * 4 + 3];
            const int o = (t >> 5) * 4 + oo;
            *(float4*)(out + ((size_t)(n * 64 + o)) * 512 + m * 128 + (t & 31) * 4) = res;
        }
    }
}

// ---------------------------------------------------------------------------
extern "C" void kernel_launch(void* const* d_in, const int* in_sizes, int n_in,
                              void* d_out, int out_size)
{
    const float* x = (const float*)d_in[0];   // [64, 1024, 128] f32
    const float* w = (const float*)d_in[1];   // [4, 64, 128] f32
    float* out = (float*)d_out;               // [64, 64, 512] f32

    cudaFuncSetAttribute(ot_fused_kernel,
                         cudaFuncAttributeMaxDynamicSharedMemorySize, SM_TOTAL);
    ot_fused_kernel<<<256, 1024, SM_TOTAL>>>(x, w, out);
}

// round 9
// speedup vs baseline: 1.5368x; 1.5368x over previous
#include <cuda_runtime.h>
#include <cuda_fp16.h>

#define IN_SIZE   1024
#define IN_DIM    128
#define OUT_SIZE  64
#define MAX_ITERS 100

// shared memory byte offsets
#define SM_MT 0                         // 65536 halves (128KB), quad-interleaved:
                                        //  (o,s) -> Mt[(o>>2)*4096 + s*4 + (o&3)]
#define SM_XS 131072                    // GEMM: [128][132] f32 padded (67584B); epilogue: [64][128] f32
#define SM_RV 198656                    // 1024 f32
#define SM_CV 202752                    // 64 f32
#define SM_FL 203008                    // 2 ints
#define SM_TOTAL 203072

__global__ __launch_bounds__(1024, 1) void ot_fused_kernel(
    const float* __restrict__ x, const float* __restrict__ w,
    float* __restrict__ out)
{
    extern __shared__ char sm[];
    __half* Mt    = (__half*)(sm + SM_MT);
    float*  xs    = (float*)(sm + SM_XS);
    float*  rv    = (float*)(sm + SM_RV);
    float*  cv    = (float*)(sm + SM_CV);
    int*    flags = (int*)(sm + SM_FL);

    const int b = blockIdx.x;
    const int n = b >> 2, m = b & 3;
    const int t = threadIdx.x;
    const int lane = t & 31, wp = t >> 5;
    const int og = t >> 6;              // 0..15  (o-quad)
    const int sl = t & 63;

    const float* xb = x + (size_t)n * IN_SIZE * IN_DIM;
    const float* wq = w + ((size_t)m * OUT_SIZE + og * 4) * IN_DIM;

    if (t == 0) { flags[0] = 0; flags[1] = 0; }
    if (t < 64) cv[t] = 1.0f;

    // ------------------------------------------------------------------
    // Phase 1: K[s,o] = x[s,:]·w[o,:];  Mt = exp(K)  (fp16, in smem)
    // 8 passes of 128 rows; thread (og, sl) computes rows {sl, sl+64} x 4 o.
    // ------------------------------------------------------------------
    for (int pr = 0; pr < 8; ++pr) {
        __syncthreads();
        const float4* xg = (const float4*)(xb + pr * 128 * IN_DIM);
#pragma unroll
        for (int jj = 0; jj < 4; ++jj) {
            int idx = jj * 1024 + t;              // 4096 float4 per pass
            float4 v = xg[idx];
            int row = idx >> 5, kq = idx & 31;
            *(float4*)(xs + row * 132 + kq * 4) = v;   // padded rows: conflict-free
        }
        __syncthreads();

        float a00=0,a01=0,a02=0,a03=0, a10=0,a11=0,a12=0,a13=0;
#pragma unroll 2
        for (int kc = 0; kc < 32; ++kc) {
            float4 xA = *(const float4*)(xs + sl        * 132 + kc * 4);
            float4 xB = *(const float4*)(xs + (sl + 64) * 132 + kc * 4);
            float4 w0 = *(const float4*)(wq + 0 * IN_DIM + kc * 4);
            float4 w1 = *(const float4*)(wq + 1 * IN_DIM + kc * 4);
            float4 w2 = *(const float4*)(wq + 2 * IN_DIM + kc * 4);
            float4 w3 = *(const float4*)(wq + 3 * IN_DIM + kc * 4);
            a00 += xA.x*w0.x + xA.y*w0.y + xA.z*w0.z + xA.w*w0.w;
            a01 += xA.x*w1.x + xA.y*w1.y + xA.z*w1.z + xA.w*w1.w;
            a02 += xA.x*w2.x + xA.y*w2.y + xA.z*w2.z + xA.w*w2.w;
            a03 += xA.x*w3.x + xA.y*w3.y + xA.z*w3.z + xA.w*w3.w;
            a10 += xB.x*w0.x + xB.y*w0.y + xB.z*w0.z + xB.w*w0.w;
            a11 += xB.x*w1.x + xB.y*w1.y + xB.z*w1.z + xB.w*w1.w;
            a12 += xB.x*w2.x + xB.y*w2.y + xB.z*w2.z + xB.w*w2.w;
            a13 += xB.x*w3.x + xB.y*w3.y + xB.z*w3.z + xB.w*w3.w;
        }
        const int S0 = pr * 128 + sl, S1 = S0 + 64;
        {
            __half2 h0 = __floats2half2_rn(__expf(a00), __expf(a01));
            __half2 h1 = __floats2half2_rn(__expf(a02), __expf(a03));
            uint2 pk; pk.x = *(unsigned*)&h0; pk.y = *(unsigned*)&h1;
            *(uint2*)(Mt + og * 4096 + S0 * 4) = pk;
        }
        {
            __half2 h0 = __floats2half2_rn(__expf(a10), __expf(a11));
            __half2 h1 = __floats2half2_rn(__expf(a12), __expf(a13));
            uint2 pk; pk.x = *(unsigned*)&h0; pk.y = *(unsigned*)&h1;
            *(uint2*)(Mt + og * 4096 + S1 * 4) = pk;
        }
    }
    __syncthreads();

    // ------------------------------------------------------------------
    // Phase 2: multiplicative Sinkhorn.  r_s = (1/16)/Σ_o M c ; c_o = 1/Σ_s M r
    // u-pass: thread t = row t.
    // v-pass: warps 0..15 each own o-quad wp over ALL 1024 rows, LDS.64
    //         conflict-free; lane 0 writes the 4 cv entries. 2 barriers/iter.
    // Early exit when c stops changing (rel tol), deterministic per CTA.
    // ------------------------------------------------------------------
    const float A = 1.0f / 16.0f;
    float r = 0.f;

    for (int it = 0; it < MAX_ITERS; ++it) {
        // u-pass: thread t = row t
        float dot = 0.f;
#pragma unroll
        for (int qq = 0; qq < 16; ++qq) {
            uint2 mm  = *(const uint2*)(Mt + qq * 4096 + t * 4);
            float4 cc = *(const float4*)(cv + qq * 4);
            float2 f0 = __half22float2(*(__half2*)&mm.x);
            float2 f1 = __half22float2(*(__half2*)&mm.y);
            dot += f0.x*cc.x + f0.y*cc.y + f1.x*cc.z + f1.y*cc.w;
        }
        r = __fdividef(A, dot);
        rv[t] = r;
        if (t == 0) flags[(it + 1) & 1] = 0;   // pre-clear next iter's flag
        __syncthreads();

        // v-pass: warp wp (<16) sums quad wp over all rows
        if (wp < 16) {
            float s0 = 0.f, s1 = 0.f, s2 = 0.f, s3 = 0.f;
#pragma unroll 8
            for (int i = 0; i < 32; ++i) {
                const int s = i * 32 + lane;
                uint2 mm = *(const uint2*)(Mt + wp * 4096 + s * 4);
                const float rr = rv[s];
                float2 f0 = __half22float2(*(__half2*)&mm.x);
                float2 f1 = __half22float2(*(__half2*)&mm.y);
                s0 += f0.x * rr; s1 += f0.y * rr; s2 += f1.x * rr; s3 += f1.y * rr;
            }
#pragma unroll
            for (int off = 16; off; off >>= 1) {
                s0 += __shfl_xor_sync(0xffffffffu, s0, off);
                s1 += __shfl_xor_sync(0xffffffffu, s1, off);
                s2 += __shfl_xor_sync(0xffffffffu, s2, off);
                s3 += __shfl_xor_sync(0xffffffffu, s3, off);
            }
            if (lane == 0) {
                const float c0 = __fdividef(1.0f, s0);
                const float c1 = __fdividef(1.0f, s1);
                const float c2 = __fdividef(1.0f, s2);
                const float c3 = __fdividef(1.0f, s3);
                const float o0 = cv[wp*4+0], o1 = cv[wp*4+1];
                const float o2 = cv[wp*4+2], o3 = cv[wp*4+3];
                cv[wp*4+0] = c0; cv[wp*4+1] = c1;
                cv[wp*4+2] = c2; cv[wp*4+3] = c3;
                const float tol = 1e-5f;
                if (fabsf(c0 - o0) > tol * fabsf(o0) ||
                    fabsf(c1 - o1) > tol * fabsf(o1) ||
                    fabsf(c2 - o2) > tol * fabsf(o2) ||
                    fabsf(c3 - o3) > tol * fabsf(o3))
                    flags[it & 1] = 1;
            }
        }
        __syncthreads();
        if (it >= 2 && flags[it & 1] == 0) break;  // converged: later iters no-ops
    }

    // ------------------------------------------------------------------
    // Phase 3: fold r, c into Mt  ->  Mt holds T = diag(r) M diag(c) (fp16)
    // ------------------------------------------------------------------
#pragma unroll
    for (int qq = 0; qq < 16; ++qq) {
        uint2 mm  = *(const uint2*)(Mt + qq * 4096 + t * 4);
        float4 cc = *(const float4*)(cv + qq * 4);
        float2 f0 = __half22float2(*(__half2*)&mm.x);
        float2 f1 = __half22float2(*(__half2*)&mm.y);
        __half2 g0 = __floats2half2_rn(f0.x * r * cc.x, f0.y * r * cc.y);
        __half2 g1 = __floats2half2_rn(f1.x * r * cc.z, f1.y * r * cc.w);
        uint2 pk; pk.x = *(unsigned*)&g0; pk.y = *(unsigned*)&g1;
        *(uint2*)(Mt + qq * 4096 + t * 4) = pk;
    }

    // ------------------------------------------------------------------
    // Phase 4: out[n, o, m*128+d] = Σ_s T[s,o] x[s,d]
    // thread tile = 4 o (one quad) x 2 d;  x staged 64 rows at a time.
    // ------------------------------------------------------------------
    const int dp = t & 63;               // d = 2*dp
    float e00=0,e01=0,e10=0,e11=0,e20=0,e21=0,e30=0,e31=0;

    for (int sb = 0; sb < 16; ++sb) {
        __syncthreads();
        const float4* xg = (const float4*)(xb + sb * 64 * IN_DIM);
        float4* xs4 = (float4*)xs;
        xs4[t]        = xg[t];
        xs4[t + 1024] = xg[t + 1024];
        __syncthreads();
#pragma unroll 4
        for (int s = 0; s < 64; ++s) {
            const int S = sb * 64 + s;
            uint2 mm = *(const uint2*)(Mt + og * 4096 + S * 4);   // broadcast
            float2 xv = *(const float2*)(xs + s * IN_DIM + dp * 2);
            float2 f0 = __half22float2(*(__half2*)&mm.x);
            float2 f1 = __half22float2(*(__half2*)&mm.y);
            e00 += f0.x * xv.x;  e01 += f0.x * xv.y;
            e10 += f0.y * xv.x;  e11 += f0.y * xv.y;
            e20 += f1.x * xv.x;  e21 += f1.x * xv.y;
            e30 += f1.y * xv.x;  e31 += f1.y * xv.y;
        }
    }
    {
        float* ob = out + ((size_t)(n * 64 + og * 4)) * 512 + m * 128 + dp * 2;
        float2 r0; r0.x = e00; r0.y = e01; *(float2*)(ob)            = r0;
        float2 r1; r1.x = e10; r1.y = e11; *(float2*)(ob + 512)      = r1;
        float2 r2; r2.x = e20; r2.y = e21; *(float2*)(ob + 1024)     = r2;
        float2 r3; r3.x = e30; r3.y = e31; *(float2*)(ob + 1536)     = r3;
    }
}

// ---------------------------------------------------------------------------
extern "C" void kernel_launch(void* const* d_in, const int* in_sizes, int n_in,
                              void* d_out, int out_size)
{
    const float* x = (const float*)d_in[0];   // [64, 1024, 128] f32
    const float* w = (const float*)d_in[1];   // [4, 64, 128] f32
    float* out = (float*)d_out;               // [64, 64, 512] f32

    cudaFuncSetAttribute(ot_fused_kernel,
                         cudaFuncAttributeMaxDynamicSharedMemorySize, SM_TOTAL);
    ot_fused_kernel<<<256, 1024, SM_TOTAL>>>(x, w, out);
}

// round 11
// speedup vs baseline: 1.5388x; 1.0013x over previous
#include <cuda_runtime.h>
#include <cuda_fp16.h>

#define IN_SIZE   1024
#define IN_DIM    128
#define OUT_SIZE  64
#define MAX_ITERS 100

// shared memory byte offsets
#define SM_MT 0                         // 65536 halves (128KB), quad-interleaved:
                                        //  (o,s) -> Mt[(o>>2)*4096 + s*4 + (o&3)]
#define SM_XS 131072                    // GEMM: [128][132] f32 padded (67584B); epilogue: [64][128] f32
#define SM_RV 198656                    // 1024 f32
#define SM_CV 202752                    // 64 f32
#define SM_FL 203008                    // 2 ints
#define SM_TOTAL 203072

__global__ __launch_bounds__(1024, 1) void ot_fused_kernel(
    const float* __restrict__ x, const float* __restrict__ w,
    float* __restrict__ out)
{
    extern __shared__ char sm[];
    __half* Mt    = (__half*)(sm + SM_MT);
    float*  xs    = (float*)(sm + SM_XS);
    float*  rv    = (float*)(sm + SM_RV);
    float*  cv    = (float*)(sm + SM_CV);
    int*    flags = (int*)(sm + SM_FL);

    const int b = blockIdx.x;
    const int n = b >> 2, m = b & 3;
    const int t = threadIdx.x;
    const int lane = t & 31, wp = t >> 5;
    const int og = t >> 6;              // 0..15  (o-quad)
    const int sl = t & 63;

    const float* xb = x + (size_t)n * IN_SIZE * IN_DIM;
    const float* wq = w + ((size_t)m * OUT_SIZE + og * 4) * IN_DIM;

    if (t == 0) { flags[0] = 0; flags[1] = 0; }
    if (t < 64) cv[t] = 1.0f;

    // ------------------------------------------------------------------
    // Phase 1: K[s,o] = x[s,:]·w[o,:];  Mt = exp(K)  (fp16, in smem)
    // 8 passes of 128 rows; thread (og, sl) computes rows {sl, sl+64} x 4 o.
    // ------------------------------------------------------------------
    for (int pr = 0; pr < 8; ++pr) {
        __syncthreads();
        const float4* xg = (const float4*)(xb + pr * 128 * IN_DIM);
#pragma unroll
        for (int jj = 0; jj < 4; ++jj) {
            int idx = jj * 1024 + t;              // 4096 float4 per pass
            float4 v = xg[idx];
            int row = idx >> 5, kq = idx & 31;
            *(float4*)(xs + row * 132 + kq * 4) = v;   // padded rows: conflict-free
        }
        __syncthreads();

        float a00=0,a01=0,a02=0,a03=0, a10=0,a11=0,a12=0,a13=0;
#pragma unroll 2
        for (int kc = 0; kc < 32; ++kc) {
            float4 xA = *(const float4*)(xs + sl        * 132 + kc * 4);
            float4 xB = *(const float4*)(xs + (sl + 64) * 132 + kc * 4);
            float4 w0 = *(const float4*)(wq + 0 * IN_DIM + kc * 4);
            float4 w1 = *(const float4*)(wq + 1 * IN_DIM + kc * 4);
            float4 w2 = *(const float4*)(wq + 2 * IN_DIM + kc * 4);
            float4 w3 = *(const float4*)(wq + 3 * IN_DIM + kc * 4);
            a00 += xA.x*w0.x + xA.y*w0.y + xA.z*w0.z + xA.w*w0.w;
            a01 += xA.x*w1.x + xA.y*w1.y + xA.z*w1.z + xA.w*w1.w;
            a02 += xA.x*w2.x + xA.y*w2.y + xA.z*w2.z + xA.w*w2.w;
            a03 += xA.x*w3.x + xA.y*w3.y + xA.z*w3.z + xA.w*w3.w;
            a10 += xB.x*w0.x + xB.y*w0.y + xB.z*w0.z + xB.w*w0.w;
            a11 += xB.x*w1.x + xB.y*w1.y + xB.z*w1.z + xB.w*w1.w;
            a12 += xB.x*w2.x + xB.y*w2.y + xB.z*w2.z + xB.w*w2.w;
            a13 += xB.x*w3.x + xB.y*w3.y + xB.z*w3.z + xB.w*w3.w;
        }
        const int S0 = pr * 128 + sl, S1 = S0 + 64;
        {
            __half2 h0 = __floats2half2_rn(__expf(a00), __expf(a01));
            __half2 h1 = __floats2half2_rn(__expf(a02), __expf(a03));
            uint2 pk; pk.x = *(unsigned*)&h0; pk.y = *(unsigned*)&h1;
            *(uint2*)(Mt + og * 4096 + S0 * 4) = pk;
        }
        {
            __half2 h0 = __floats2half2_rn(__expf(a10), __expf(a11));
            __half2 h1 = __floats2half2_rn(__expf(a12), __expf(a13));
            uint2 pk; pk.x = *(unsigned*)&h0; pk.y = *(unsigned*)&h1;
            *(uint2*)(Mt + og * 4096 + S1 * 4) = pk;
        }
    }
    __syncthreads();

    // ------------------------------------------------------------------
    // Phase 2: multiplicative Sinkhorn.  r_s = (1/16)/Σ_o M c ; c_o = 1/Σ_s M r
    // u-pass: thread t = row t.
    // v-pass: warps 0..15 each own o-quad wp over ALL 1024 rows, LDS.64
    //         conflict-free; lane 0 writes the 4 cv entries. 2 barriers/iter.
    // Early exit when c stops changing (rel tol), deterministic per CTA.
    // ------------------------------------------------------------------
    const float A = 1.0f / 16.0f;
    float r = 0.f;

    for (int it = 0; it < MAX_ITERS; ++it) {
        // u-pass: thread t = row t
        float dot = 0.f;
#pragma unroll
        for (int qq = 0; qq < 16; ++qq) {
            uint2 mm  = *(const uint2*)(Mt + qq * 4096 + t * 4);
            float4 cc = *(const float4*)(cv + qq * 4);
            float2 f0 = __half22float2(*(__half2*)&mm.x);
            float2 f1 = __half22float2(*(__half2*)&mm.y);
            dot += f0.x*cc.x + f0.y*cc.y + f1.x*cc.z + f1.y*cc.w;
        }
        r = __fdividef(A, dot);
        rv[t] = r;
        if (t == 0) flags[(it + 1) & 1] = 0;   // pre-clear next iter's flag
        __syncthreads();

        // v-pass: warp wp (<16) sums quad wp over all rows
        if (wp < 16) {
            float s0 = 0.f, s1 = 0.f, s2 = 0.f, s3 = 0.f;
#pragma unroll 8
            for (int i = 0; i < 32; ++i) {
                const int s = i * 32 + lane;
                uint2 mm = *(const uint2*)(Mt + wp * 4096 + s * 4);
                const float rr = rv[s];
                float2 f0 = __half22float2(*(__half2*)&mm.x);
                float2 f1 = __half22float2(*(__half2*)&mm.y);
                s0 += f0.x * rr; s1 += f0.y * rr; s2 += f1.x * rr; s3 += f1.y * rr;
            }
#pragma unroll
            for (int off = 16; off; off >>= 1) {
                s0 += __shfl_xor_sync(0xffffffffu, s0, off);
                s1 += __shfl_xor_sync(0xffffffffu, s1, off);
                s2 += __shfl_xor_sync(0xffffffffu, s2, off);
                s3 += __shfl_xor_sync(0xffffffffu, s3, off);
            }
            if (lane == 0) {
                const float c0 = __fdividef(1.0f, s0);
                const float c1 = __fdividef(1.0f, s1);
                const float c2 = __fdividef(1.0f, s2);
                const float c3 = __fdividef(1.0f, s3);
                const float o0 = cv[wp*4+0], o1 = cv[wp*4+1];
                const float o2 = cv[wp*4+2], o3 = cv[wp*4+3];
                cv[wp*4+0] = c0; cv[wp*4+1] = c1;
                cv[wp*4+2] = c2; cv[wp*4+3] = c3;
                const float tol = 1e-5f;
                if (fabsf(c0 - o0) > tol * fabsf(o0) ||
                    fabsf(c1 - o1) > tol * fabsf(o1) ||
                    fabsf(c2 - o2) > tol * fabsf(o2) ||
                    fabsf(c3 - o3) > tol * fabsf(o3))
                    flags[it & 1] = 1;
            }
        }
        __syncthreads();
        if (it >= 2 && flags[it & 1] == 0) break;  // converged: later iters no-ops
    }

    // ------------------------------------------------------------------
    // Phase 3: fold r, c into Mt  ->  Mt holds T = diag(r) M diag(c) (fp16)
    // ------------------------------------------------------------------
#pragma unroll
    for (int qq = 0; qq < 16; ++qq) {
        uint2 mm  = *(const uint2*)(Mt + qq * 4096 + t * 4);
        float4 cc = *(const float4*)(cv + qq * 4);
        float2 f0 = __half22float2(*(__half2*)&mm.x);
        float2 f1 = __half22float2(*(__half2*)&mm.y);
        __half2 g0 = __floats2half2_rn(f0.x * r * cc.x, f0.y * r * cc.y);
        __half2 g1 = __floats2half2_rn(f1.x * r * cc.z, f1.y * r * cc.w);
        uint2 pk; pk.x = *(unsigned*)&g0; pk.y = *(unsigned*)&g1;
        *(uint2*)(Mt + qq * 4096 + t * 4) = pk;
    }

    // ------------------------------------------------------------------
    // Phase 4: out[n, o, m*128+d] = Σ_s T[s,o] x[s,d]
    // thread tile = 4 o (one quad) x 2 d;  x staged 64 rows at a time.
    // ------------------------------------------------------------------
    const int dp = t & 63;               // d = 2*dp
    float e00=0,e01=0,e10=0,e11=0,e20=0,e21=0,e30=0,e31=0;

    for (int sb = 0; sb < 16; ++sb) {
        __syncthreads();
        const float4* xg = (const float4*)(xb + sb * 64 * IN_DIM);
        float4* xs4 = (float4*)xs;
        xs4[t]        = xg[t];
        xs4[t + 1024] = xg[t + 1024];
        __syncthreads();
#pragma unroll 4
        for (int s = 0; s < 64; ++s) {
            const int S = sb * 64 + s;
            uint2 mm = *(const uint2*)(Mt + og * 4096 + S * 4);   // broadcast
            float2 xv = *(const float2*)(xs + s * IN_DIM + dp * 2);
            float2 f0 = __half22float2(*(__half2*)&mm.x);
            float2 f1 = __half22float2(*(__half2*)&mm.y);
            e00 += f0.x * xv.x;  e01 += f0.x * xv.y;
            e10 += f0.y * xv.x;  e11 += f0.y * xv.y;
            e20 += f1.x * xv.x;  e21 += f1.x * xv.y;
            e30 += f1.y * xv.x;  e31 += f1.y * xv.y;
        }
    }
    {
        float* ob = out + ((size_t)(n * 64 + og * 4)) * 512 + m * 128 + dp * 2;
        float2 r0; r0.x = e00; r0.y = e01; *(float2*)(ob)            = r0;
        float2 r1; r1.x = e10; r1.y = e11; *(float2*)(ob + 512)      = r1;
        float2 r2; r2.x = e20; r2.y = e21; *(float2*)(ob + 1024)     = r2;
        float2 r3; r3.x = e30; r3.y = e31; *(float2*)(ob + 1536)     = r3;
    }
}

// ---------------------------------------------------------------------------
extern "C" void kernel_launch(void* const* d_in, const int* in_sizes, int n_in,
                              void* d_out, int out_size)
{
    const float* x = (const float*)d_in[0];   // [64, 1024, 128] f32
    const float* w = (const float*)d_in[1];   // [4, 64, 128] f32
    float* out = (float*)d_out;               // [64, 64, 512] f32

    cudaFuncSetAttribute(ot_fused_kernel,
                         cudaFuncAttributeMaxDynamicSharedMemorySize, SM_TOTAL);
    ot_fused_kernel<<<256, 1024, SM_TOTAL>>>(x, w, out);
}

// round 12
// speedup vs baseline: 5.1368x; 3.3383x over previous
#include <cuda_runtime.h>
#include <cuda_fp16.h>

#define IN_SIZE   1024
#define IN_DIM    128
#define MAX_ITERS 100

// smem byte offsets
#define SM_MT 0           // M/T row-major fp16: 1024 rows x 144B stride (128B data)
#define MT_STRIDE 144
#define SM_XS 147456      // x chunk fp16: 128 rows x 272B stride (256B data)
#define XS_STRIDE 272
#define SM_W  182272      // w fp16: 64 rows x 272B stride
#define W_STRIDE 272
#define SM_RV 199680      // 1024 f32
#define SM_CV 203776      // 64 f32
#define SM_FL 204032      // 2 ints
#define SM_TOTAL 204096

__device__ __forceinline__ unsigned smem_u32(const void* p) {
    return (unsigned)__cvta_generic_to_shared(p);
}
__device__ __forceinline__ void ldsm4(unsigned& r0, unsigned& r1, unsigned& r2,
                                      unsigned& r3, unsigned a) {
    asm volatile("ldmatrix.sync.aligned.m8n8.x4.shared.b16 {%0,%1,%2,%3}, [%4];"
                 : "=r"(r0), "=r"(r1), "=r"(r2), "=r"(r3) : "r"(a));
}
__device__ __forceinline__ void ldsm4t(unsigned& r0, unsigned& r1, unsigned& r2,
                                       unsigned& r3, unsigned a) {
    asm volatile("ldmatrix.sync.aligned.m8n8.x4.trans.shared.b16 {%0,%1,%2,%3}, [%4];"
                 : "=r"(r0), "=r"(r1), "=r"(r2), "=r"(r3) : "r"(a));
}
__device__ __forceinline__ void mma16816(float* c, unsigned a0, unsigned a1,
                                         unsigned a2, unsigned a3,
                                         unsigned b0, unsigned b1) {
    asm volatile("mma.sync.aligned.m16n8k16.row.col.f32.f16.f16.f32 "
                 "{%0,%1,%2,%3}, {%4,%5,%6,%7}, {%8,%9}, {%0,%1,%2,%3};"
                 : "+f"(c[0]), "+f"(c[1]), "+f"(c[2]), "+f"(c[3])
                 : "r"(a0), "r"(a1), "r"(a2), "r"(a3), "r"(b0), "r"(b1));
}
__device__ __forceinline__ unsigned h2u(__half2 h) { return *(unsigned*)&h; }

// stage x chunk ch (128 rows) -> XS fp16, 272B stride.  All 1024 threads.
__device__ __forceinline__ void stage_x(char* sm, const float* xb, int ch, int t) {
    const float4* xg = (const float4*)(xb + ch * 128 * IN_DIM);
    const int row = t >> 3, c8 = t & 7;
    float4 v0 = xg[row * 32 + c8 * 4 + 0];
    float4 v1 = xg[row * 32 + c8 * 4 + 1];
    float4 v2 = xg[row * 32 + c8 * 4 + 2];
    float4 v3 = xg[row * 32 + c8 * 4 + 3];
    uint4 p0, p1;
    p0.x = h2u(__floats2half2_rn(v0.x, v0.y));
    p0.y = h2u(__floats2half2_rn(v0.z, v0.w));
    p0.z = h2u(__floats2half2_rn(v1.x, v1.y));
    p0.w = h2u(__floats2half2_rn(v1.z, v1.w));
    p1.x = h2u(__floats2half2_rn(v2.x, v2.y));
    p1.y = h2u(__floats2half2_rn(v2.z, v2.w));
    p1.z = h2u(__floats2half2_rn(v3.x, v3.y));
    p1.w = h2u(__floats2half2_rn(v3.z, v3.w));
    char* dst = sm + SM_XS + row * XS_STRIDE + c8 * 32;
    *(uint4*)dst = p0;
    *(uint4*)(dst + 16) = p1;
}

__global__ __launch_bounds__(1024, 1) void ot_fused_kernel(
    const float* __restrict__ x, const float* __restrict__ w,
    float* __restrict__ out)
{
    extern __shared__ char sm[];
    float* rv    = (float*)(sm + SM_RV);
    float* cv    = (float*)(sm + SM_CV);
    int*   flags = (int*)(sm + SM_FL);

    const int b = blockIdx.x;
    const int n = b >> 2, m = b & 3;
    const int t = threadIdx.x;
    const int lane = t & 31, wp = t >> 5;

    const float* xb = x + (size_t)n * IN_SIZE * IN_DIM;
    const unsigned MT_u = smem_u32(sm + SM_MT);
    const unsigned XS_u = smem_u32(sm + SM_XS);
    const unsigned W_u  = smem_u32(sm + SM_W);

    if (t == 0) { flags[0] = 0; flags[1] = 0; }
    if (t < 64) cv[t] = 1.0f;

    // stage w -> fp16 (64 rows x 128 halves, 272B stride)
    {
        const float* wb = w + (size_t)m * 64 * IN_DIM;
        const int row = t >> 4, c16 = t & 15;
        const float4* wg = (const float4*)(wb + row * IN_DIM + c16 * 8);
        float4 v0 = wg[0], v1 = wg[1];
        uint4 pk;
        pk.x = h2u(__floats2half2_rn(v0.x, v0.y));
        pk.y = h2u(__floats2half2_rn(v0.z, v0.w));
        pk.z = h2u(__floats2half2_rn(v1.x, v1.y));
        pk.w = h2u(__floats2half2_rn(v1.z, v1.w));
        *(uint4*)(sm + SM_W + row * W_STRIDE + c16 * 16) = pk;
    }

    // ------------------------------------------------------------------
    // Phase 1: M[s,o] = exp(x[s,:].w[o,:])  via HMMA m16n8k16
    // warp: mt = wp>>2 (16-row s-tile in chunk), o0 = (wp&3)*16
    // ------------------------------------------------------------------
    {
        const int mt = wp >> 2;
        const int o0 = (wp & 3) * 16;
        const unsigned aB = XS_u + (mt * 16 + (lane & 15)) * XS_STRIDE
                          + (lane >> 4) * 16;
        const unsigned bB = W_u + (o0 + (lane & 7) + (lane >> 4) * 8) * W_STRIDE
                          + ((lane >> 3) & 1) * 16;
        for (int ch = 0; ch < 8; ++ch) {
            __syncthreads();
            stage_x(sm, xb, ch, t);
            __syncthreads();

            float c0[4] = {0.f,0.f,0.f,0.f}, c1[4] = {0.f,0.f,0.f,0.f};
#pragma unroll
            for (int kk = 0; kk < 8; ++kk) {
                unsigned a0,a1,a2,a3, b0,b1,b2,b3;
                ldsm4(a0, a1, a2, a3, aB + kk * 32);
                ldsm4(b0, b1, b2, b3, bB + kk * 32);
                mma16816(c0, a0, a1, a2, a3, b0, b1);
                mma16816(c1, a0, a1, a2, a3, b2, b3);
            }
            const int sb = ch * 128 + mt * 16 + (lane >> 2);
            const int ob = o0 + 2 * (lane & 3);
            __half* r0p = (__half*)(sm + SM_MT + sb * MT_STRIDE);
            __half* r1p = (__half*)(sm + SM_MT + (sb + 8) * MT_STRIDE);
            *(unsigned*)(r0p + ob)     = h2u(__floats2half2_rn(__expf(c0[0]), __expf(c0[1])));
            *(unsigned*)(r1p + ob)     = h2u(__floats2half2_rn(__expf(c0[2]), __expf(c0[3])));
            *(unsigned*)(r0p + ob + 8) = h2u(__floats2half2_rn(__expf(c1[0]), __expf(c1[1])));
            *(unsigned*)(r1p + ob + 8) = h2u(__floats2half2_rn(__expf(c1[2]), __expf(c1[3])));
        }
    }
    __syncthreads();

    // ------------------------------------------------------------------
    // Phase 2: multiplicative Sinkhorn on row-major M.
    // u-pass: thread t = row t (8x LDS.128).  v-pass: warps 0..7, warp wp
    // owns o-chunk [8wp,8wp+8) over all rows (16B reads, 4-wf optimal).
    // ------------------------------------------------------------------
    const float A = 1.0f / 16.0f;
    float r = 0.f;

    for (int it = 0; it < MAX_ITERS; ++it) {
        const char* mrow = sm + SM_MT + t * MT_STRIDE;
        float dot = 0.f;
#pragma unroll
        for (int c = 0; c < 8; ++c) {
            uint4 mm  = *(const uint4*)(mrow + c * 16);
            float4 cA = *(const float4*)(cv + c * 8);
            float4 cB = *(const float4*)(cv + c * 8 + 4);
            float2 f0 = __half22float2(*(__half2*)&mm.x);
            float2 f1 = __half22float2(*(__half2*)&mm.y);
            float2 f2 = __half22float2(*(__half2*)&mm.z);
            float2 f3 = __half22float2(*(__half2*)&mm.w);
            dot += f0.x*cA.x + f0.y*cA.y + f1.x*cA.z + f1.y*cA.w
                 + f2.x*cB.x + f2.y*cB.y + f3.x*cB.z + f3.y*cB.w;
        }
        r = __fdividef(A, dot);
        rv[t] = r;
        if (t == 0) flags[(it + 1) & 1] = 0;
        __syncthreads();

        if (wp < 8) {
            float s0=0,s1=0,s2=0,s3=0,s4=0,s5=0,s6=0,s7=0;
#pragma unroll 4
            for (int i = 0; i < 32; ++i) {
                const int s = i * 32 + lane;
                uint4 mm = *(const uint4*)(sm + SM_MT + s * MT_STRIDE + wp * 16);
                const float rr = rv[s];
                float2 f0 = __half22float2(*(__half2*)&mm.x);
                float2 f1 = __half22float2(*(__half2*)&mm.y);
                float2 f2 = __half22float2(*(__half2*)&mm.z);
                float2 f3 = __half22float2(*(__half2*)&mm.w);
                s0 += f0.x*rr; s1 += f0.y*rr; s2 += f1.x*rr; s3 += f1.y*rr;
                s4 += f2.x*rr; s5 += f2.y*rr; s6 += f3.x*rr; s7 += f3.y*rr;
            }
#pragma unroll
            for (int off = 16; off; off >>= 1) {
                s0 += __shfl_xor_sync(~0u, s0, off);
                s1 += __shfl_xor_sync(~0u, s1, off);
                s2 += __shfl_xor_sync(~0u, s2, off);
                s3 += __shfl_xor_sync(~0u, s3, off);
                s4 += __shfl_xor_sync(~0u, s4, off);
                s5 += __shfl_xor_sync(~0u, s5, off);
                s6 += __shfl_xor_sync(~0u, s6, off);
                s7 += __shfl_xor_sync(~0u, s7, off);
            }
            if (lane == 0) {
                float nc[8];
                nc[0]=__fdividef(1.f,s0); nc[1]=__fdividef(1.f,s1);
                nc[2]=__fdividef(1.f,s2); nc[3]=__fdividef(1.f,s3);
                nc[4]=__fdividef(1.f,s4); nc[5]=__fdividef(1.f,s5);
                nc[6]=__fdividef(1.f,s6); nc[7]=__fdividef(1.f,s7);
                const float tol = 1e-5f;
                bool chg = false;
#pragma unroll
                for (int j = 0; j < 8; ++j) {
                    const float o = cv[wp * 8 + j];
                    if (fabsf(nc[j] - o) > tol * fabsf(o)) chg = true;
                    cv[wp * 8 + j] = nc[j];
                }
                if (chg) flags[it & 1] = 1;
            }
        }
        __syncthreads();
        if (it >= 2 && flags[it & 1] == 0) break;
    }

    // ------------------------------------------------------------------
    // Phase 3: fold r, c into T in place (row rescale, no transpose)
    // ------------------------------------------------------------------
    {
        char* mrow = sm + SM_MT + t * MT_STRIDE;
#pragma unroll
        for (int c = 0; c < 8; ++c) {
            uint4 mm  = *(const uint4*)(mrow + c * 16);
            float4 cA = *(const float4*)(cv + c * 8);
            float4 cB = *(const float4*)(cv + c * 8 + 4);
            float2 f0 = __half22float2(*(__half2*)&mm.x);
            float2 f1 = __half22float2(*(__half2*)&mm.y);
            float2 f2 = __half22float2(*(__half2*)&mm.z);
            float2 f3 = __half22float2(*(__half2*)&mm.w);
            uint4 pk;
            pk.x = h2u(__floats2half2_rn(f0.x*r*cA.x, f0.y*r*cA.y));
            pk.y = h2u(__floats2half2_rn(f1.x*r*cA.z, f1.y*r*cA.w));
            pk.z = h2u(__floats2half2_rn(f2.x*r*cB.x, f2.y*r*cB.y));
            pk.w = h2u(__floats2half2_rn(f3.x*r*cB.z, f3.y*r*cB.w));
            *(uint4*)(mrow + c * 16) = pk;
        }
    }
    __syncthreads();

    // ------------------------------------------------------------------
    // Phase 4: out[o,d] = sum_s T[s,o] x[s,d]  via HMMA
    // A = T^T (ldmatrix.trans on T rows), B = x (ldmatrix.trans on x rows)
    // warp: mt4 = wp>>3 (16-row o-tile), dgrp = wp&7 (16 d columns)
    // ------------------------------------------------------------------
    {
        const int mt4 = wp >> 3, dgrp = wp & 7;
        float e0[4] = {0.f,0.f,0.f,0.f}, e1[4] = {0.f,0.f,0.f,0.f};
        const unsigned aOff = (mt4 * 2 + ((lane >> 3) & 1)) * 16;
        const unsigned aRow = (lane & 7) + (lane >> 4) * 8;
        const unsigned bB = XS_u
            + ((lane & 7) + ((lane >> 3) & 1) * 8) * XS_STRIDE
            + (dgrp * 2 + (lane >> 4)) * 16;

        for (int ch = 0; ch < 8; ++ch) {
            __syncthreads();
            stage_x(sm, xb, ch, t);
            __syncthreads();
#pragma unroll
            for (int kk = 0; kk < 8; ++kk) {
                unsigned a0,a1,a2,a3, b0,b1,b2,b3;
                const unsigned sg = ch * 128 + kk * 16;
                ldsm4t(a0, a1, a2, a3, MT_u + (sg + aRow) * MT_STRIDE + aOff);
                ldsm4t(b0, b1, b2, b3, bB + kk * 16 * XS_STRIDE);
                mma16816(e0, a0, a1, a2, a3, b0, b1);
                mma16816(e1, a0, a1, a2, a3, b2, b3);
            }
        }
        const int o  = mt4 * 16 + (lane >> 2);
        const int db = dgrp * 16 + 2 * (lane & 3);
        float* ob0 = out + ((size_t)(n * 64 + o)) * 512 + m * 128;
        float* ob1 = out + ((size_t)(n * 64 + o + 8)) * 512 + m * 128;
        float2 v;
        v.x = e0[0]; v.y = e0[1]; *(float2*)(ob0 + db)     = v;
        v.x = e0[2]; v.y = e0[3]; *(float2*)(ob1 + db)     = v;
        v.x = e1[0]; v.y = e1[1]; *(float2*)(ob0 + db + 8) = v;
        v.x = e1[2]; v.y = e1[3]; *(float2*)(ob1 + db + 8) = v;
    }
}

// ---------------------------------------------------------------------------
extern "C" void kernel_launch(void* const* d_in, const int* in_sizes, int n_in,
                              void* d_out, int out_size)
{
    const float* x = (const float*)d_in[0];   // [64, 1024, 128] f32
    const float* w = (const float*)d_in[1];   // [4, 64, 128] f32
    float* out = (float*)d_out;               // [64, 64, 512] f32

    cudaFuncSetAttribute(ot_fused_kernel,
                         cudaFuncAttributeMaxDynamicSharedMemorySize, SM_TOTAL);
    ot_fused_kernel<<<256, 1024, SM_TOTAL>>>(x, w, out);
}

// round 15
// speedup vs baseline: 5.6945x; 1.1086x over previous
#include <cuda_runtime.h>
#include <cuda_fp16.h>

#define IN_SIZE   1024
#define IN_DIM    128
#define MAX_ITERS 100

// smem byte offsets
#define SM_MT 0           // M/T row-major fp16: 1024 rows x 144B stride (128B data)
#define MT_STRIDE 144
#define SM_XS 147456      // x chunk fp16: 128 rows x 272B stride (256B data)
#define XS_STRIDE 272
#define SM_W  182272      // w fp16: 64 rows x 272B stride
#define W_STRIDE 272
#define SM_RV 199680      // 1024 f32
#define SM_CV 203776      // 64 f32
#define SM_FL 204032      // 2 ints
#define SM_TOTAL 204096

__device__ __forceinline__ unsigned smem_u32(const void* p) {
    return (unsigned)__cvta_generic_to_shared(p);
}
__device__ __forceinline__ void ldsm4(unsigned& r0, unsigned& r1, unsigned& r2,
                                      unsigned& r3, unsigned a) {
    asm volatile("ldmatrix.sync.aligned.m8n8.x4.shared.b16 {%0,%1,%2,%3}, [%4];"
                 : "=r"(r0), "=r"(r1), "=r"(r2), "=r"(r3) : "r"(a));
}
__device__ __forceinline__ void ldsm4t(unsigned& r0, unsigned& r1, unsigned& r2,
                                       unsigned& r3, unsigned a) {
    asm volatile("ldmatrix.sync.aligned.m8n8.x4.trans.shared.b16 {%0,%1,%2,%3}, [%4];"
                 : "=r"(r0), "=r"(r1), "=r"(r2), "=r"(r3) : "r"(a));
}
__device__ __forceinline__ void mma16816(float* c, unsigned a0, unsigned a1,
                                         unsigned a2, unsigned a3,
                                         unsigned b0, unsigned b1) {
    asm volatile("mma.sync.aligned.m16n8k16.row.col.f32.f16.f16.f32 "
                 "{%0,%1,%2,%3}, {%4,%5,%6,%7}, {%8,%9}, {%0,%1,%2,%3};"
                 : "+f"(c[0]), "+f"(c[1]), "+f"(c[2]), "+f"(c[3])
                 : "r"(a0), "r"(a1), "r"(a2), "r"(a3), "r"(b0), "r"(b1));
}
__device__ __forceinline__ unsigned h2u(__half2 h) { return *(unsigned*)&h; }

// stage x chunk ch (128 rows) -> XS fp16, 272B stride.  All 1024 threads.
__device__ __forceinline__ void stage_x(char* sm, const float* xb, int ch, int t) {
    const float4* xg = (const float4*)(xb + ch * 128 * IN_DIM);
    const int row = t >> 3, c8 = t & 7;
    float4 v0 = xg[row * 32 + c8 * 4 + 0];
    float4 v1 = xg[row * 32 + c8 * 4 + 1];
    float4 v2 = xg[row * 32 + c8 * 4 + 2];
    float4 v3 = xg[row * 32 + c8 * 4 + 3];
    uint4 p0, p1;
    p0.x = h2u(__floats2half2_rn(v0.x, v0.y));
    p0.y = h2u(__floats2half2_rn(v0.z, v0.w));
    p0.z = h2u(__floats2half2_rn(v1.x, v1.y));
    p0.w = h2u(__floats2half2_rn(v1.z, v1.w));
    p1.x = h2u(__floats2half2_rn(v2.x, v2.y));
    p1.y = h2u(__floats2half2_rn(v2.z, v2.w));
    p1.z = h2u(__floats2half2_rn(v3.x, v3.y));
    p1.w = h2u(__floats2half2_rn(v3.z, v3.w));
    char* dst = sm + SM_XS + row * XS_STRIDE + c8 * 32;
    *(uint4*)dst = p0;
    *(uint4*)(dst + 16) = p1;
}

__global__ __launch_bounds__(1024, 1) void ot_fused_kernel(
    const float* __restrict__ x, const float* __restrict__ w,
    float* __restrict__ out)
{
    extern __shared__ char sm[];
    float* rv    = (float*)(sm + SM_RV);
    float* cv    = (float*)(sm + SM_CV);
    int*   flags = (int*)(sm + SM_FL);

    const int b = blockIdx.x;
    const int n = b >> 2, m = b & 3;
    const int t = threadIdx.x;
    const int lane = t & 31, wp = t >> 5;

    const float* xb = x + (size_t)n * IN_SIZE * IN_DIM;
    const unsigned MT_u = smem_u32(sm + SM_MT);
    const unsigned XS_u = smem_u32(sm + SM_XS);
    const unsigned W_u  = smem_u32(sm + SM_W);

    if (t == 0) { flags[0] = 0; flags[1] = 0; }
    if (t < 64) cv[t] = 1.0f;

    // stage w -> fp16 (64 rows x 128 halves, 272B stride)
    {
        const float* wb = w + (size_t)m * 64 * IN_DIM;
        const int row = t >> 4, c16 = t & 15;
        const float4* wg = (const float4*)(wb + row * IN_DIM + c16 * 8);
        float4 v0 = wg[0], v1 = wg[1];
        uint4 pk;
        pk.x = h2u(__floats2half2_rn(v0.x, v0.y));
        pk.y = h2u(__floats2half2_rn(v0.z, v0.w));
        pk.z = h2u(__floats2half2_rn(v1.x, v1.y));
        pk.w = h2u(__floats2half2_rn(v1.z, v1.w));
        *(uint4*)(sm + SM_W + row * W_STRIDE + c16 * 16) = pk;
    }

    // ------------------------------------------------------------------
    // Phase 1: M[s,o] = exp(x[s,:].w[o,:])  via HMMA, warp tile m32 x n32.
    // 8 compute warps: wm = wp&3 (32-row s-strip), wn = wp>>2 (32-col o-strip)
    // ------------------------------------------------------------------
    {
        const int wm = wp & 3, wn = (wp >> 2) & 1;
        const unsigned aB0 = XS_u + (wm * 32 + (lane & 15)) * XS_STRIDE
                           + (lane >> 4) * 16;
        const unsigned aB1 = aB0 + 16 * XS_STRIDE;
        const unsigned bB0 = W_u + (wn * 32 + (lane & 7) + (lane >> 4) * 8) * W_STRIDE
                           + ((lane >> 3) & 1) * 16;
        const unsigned bB1 = bB0 + 16 * W_STRIDE;

        for (int ch = 0; ch < 8; ++ch) {
            __syncthreads();
            stage_x(sm, xb, ch, t);
            __syncthreads();
            if (wp < 8) {
                float e[2][4][4];
#pragma unroll
                for (int mi = 0; mi < 2; ++mi)
#pragma unroll
                    for (int ni = 0; ni < 4; ++ni)
#pragma unroll
                        for (int f = 0; f < 4; ++f) e[mi][ni][f] = 0.f;
#pragma unroll
                for (int kk = 0; kk < 8; ++kk) {
                    unsigned a[8], bq[8];
                    ldsm4(a[0], a[1], a[2], a[3], aB0 + kk * 32);
                    ldsm4(a[4], a[5], a[6], a[7], aB1 + kk * 32);
                    ldsm4(bq[0], bq[1], bq[2], bq[3], bB0 + kk * 32);
                    ldsm4(bq[4], bq[5], bq[6], bq[7], bB1 + kk * 32);
#pragma unroll
                    for (int mi = 0; mi < 2; ++mi)
#pragma unroll
                        for (int ni = 0; ni < 4; ++ni)
                            mma16816(e[mi][ni], a[mi*4], a[mi*4+1], a[mi*4+2],
                                     a[mi*4+3], bq[2*ni], bq[2*ni+1]);
                }
#pragma unroll
                for (int mi = 0; mi < 2; ++mi) {
                    const int sb = ch * 128 + wm * 32 + mi * 16 + (lane >> 2);
                    __half* r0p = (__half*)(sm + SM_MT + sb * MT_STRIDE);
                    __half* r1p = (__half*)(sm + SM_MT + (sb + 8) * MT_STRIDE);
#pragma unroll
                    for (int ni = 0; ni < 4; ++ni) {
                        const int ob = wn * 32 + ni * 8 + 2 * (lane & 3);
                        *(unsigned*)(r0p + ob) =
                            h2u(__floats2half2_rn(__expf(e[mi][ni][0]), __expf(e[mi][ni][1])));
                        *(unsigned*)(r1p + ob) =
                            h2u(__floats2half2_rn(__expf(e[mi][ni][2]), __expf(e[mi][ni][3])));
                    }
                }
            }
        }
    }
    __syncthreads();

    // ------------------------------------------------------------------
    // Phase 2: multiplicative Sinkhorn on row-major M.
    // ------------------------------------------------------------------
    const float A = 1.0f / 16.0f;
    float r = 0.f;

    for (int it = 0; it < MAX_ITERS; ++it) {
        const char* mrow = sm + SM_MT + t * MT_STRIDE;
        float dot = 0.f;
#pragma unroll
        for (int c = 0; c < 8; ++c) {
            uint4 mm  = *(const uint4*)(mrow + c * 16);
            float4 cA = *(const float4*)(cv + c * 8);
            float4 cB = *(const float4*)(cv + c * 8 + 4);
            float2 f0 = __half22float2(*(__half2*)&mm.x);
            float2 f1 = __half22float2(*(__half2*)&mm.y);
            float2 f2 = __half22float2(*(__half2*)&mm.z);
            float2 f3 = __half22float2(*(__half2*)&mm.w);
            dot += f0.x*cA.x + f0.y*cA.y + f1.x*cA.z + f1.y*cA.w
                 + f2.x*cB.x + f2.y*cB.y + f3.x*cB.z + f3.y*cB.w;
        }
        r = __fdividef(A, dot);
        rv[t] = r;
        if (t == 0) flags[(it + 1) & 1] = 0;
        __syncthreads();

        if (wp < 8) {
            float s0=0,s1=0,s2=0,s3=0,s4=0,s5=0,s6=0,s7=0;
#pragma unroll 4
            for (int i = 0; i < 32; ++i) {
                const int s = i * 32 + lane;
                uint4 mm = *(const uint4*)(sm + SM_MT + s * MT_STRIDE + wp * 16);
                const float rr = rv[s];
                float2 f0 = __half22float2(*(__half2*)&mm.x);
                float2 f1 = __half22float2(*(__half2*)&mm.y);
                float2 f2 = __half22float2(*(__half2*)&mm.z);
                float2 f3 = __half22float2(*(__half2*)&mm.w);
                s0 += f0.x*rr; s1 += f0.y*rr; s2 += f1.x*rr; s3 += f1.y*rr;
                s4 += f2.x*rr; s5 += f2.y*rr; s6 += f3.x*rr; s7 += f3.y*rr;
            }
#pragma unroll
            for (int off = 16; off; off >>= 1) {
                s0 += __shfl_xor_sync(~0u, s0, off);
                s1 += __shfl_xor_sync(~0u, s1, off);
                s2 += __shfl_xor_sync(~0u, s2, off);
                s3 += __shfl_xor_sync(~0u, s3, off);
                s4 += __shfl_xor_sync(~0u, s4, off);
                s5 += __shfl_xor_sync(~0u, s5, off);
                s6 += __shfl_xor_sync(~0u, s6, off);
                s7 += __shfl_xor_sync(~0u, s7, off);
            }
            if (lane == 0) {
                float nc[8];
                nc[0]=__fdividef(1.f,s0); nc[1]=__fdividef(1.f,s1);
                nc[2]=__fdividef(1.f,s2); nc[3]=__fdividef(1.f,s3);
                nc[4]=__fdividef(1.f,s4); nc[5]=__fdividef(1.f,s5);
                nc[6]=__fdividef(1.f,s6); nc[7]=__fdividef(1.f,s7);
                const float tol = 5e-5f;
                bool chg = false;
#pragma unroll
                for (int j = 0; j < 8; ++j) {
                    const float o = cv[wp * 8 + j];
                    if (fabsf(nc[j] - o) > tol * fabsf(o)) chg = true;
                    cv[wp * 8 + j] = nc[j];
                }
                if (chg) flags[it & 1] = 1;
            }
        }
        __syncthreads();
        if (it >= 2 && flags[it & 1] == 0) break;
    }

    // ------------------------------------------------------------------
    // Phase 3: fold r, c into T in place (row rescale)
    // ------------------------------------------------------------------
    {
        char* mrow = sm + SM_MT + t * MT_STRIDE;
#pragma unroll
        for (int c = 0; c < 8; ++c) {
            uint4 mm  = *(const uint4*)(mrow + c * 16);
            float4 cA = *(const float4*)(cv + c * 8);
            float4 cB = *(const float4*)(cv + c * 8 + 4);
            float2 f0 = __half22float2(*(__half2*)&mm.x);
            float2 f1 = __half22float2(*(__half2*)&mm.y);
            float2 f2 = __half22float2(*(__half2*)&mm.z);
            float2 f3 = __half22float2(*(__half2*)&mm.w);
            uint4 pk;
            pk.x = h2u(__floats2half2_rn(f0.x*r*cA.x, f0.y*r*cA.y));
            pk.y = h2u(__floats2half2_rn(f1.x*r*cA.z, f1.y*r*cA.w));
            pk.z = h2u(__floats2half2_rn(f2.x*r*cB.x, f2.y*r*cB.y));
            pk.w = h2u(__floats2half2_rn(f3.x*r*cB.z, f3.y*r*cB.w));
            *(uint4*)(mrow + c * 16) = pk;
        }
    }
    __syncthreads();

    // ------------------------------------------------------------------
    // Phase 4: out[o,d] = sum_s T[s,o] x[s,d]  via HMMA, warp tile m32 x n32.
    // 8 compute warps: wo = wp&1 (32-o strip), wd = wp>>1 (32-d strip)
    // A = T^T (ldsm.trans on T rows), B = x (ldsm.trans on x rows)
    // ------------------------------------------------------------------
    {
        const int wo = wp & 1, wd = (wp >> 1) & 3;
        float e[2][4][4];
#pragma unroll
        for (int mi = 0; mi < 2; ++mi)
#pragma unroll
            for (int ni = 0; ni < 4; ++ni)
#pragma unroll
                for (int f = 0; f < 4; ++f) e[mi][ni][f] = 0.f;

        const unsigned aRow = (lane & 7) + (lane >> 4) * 8;
        const unsigned aOff0 = (wo * 4 + ((lane >> 3) & 1)) * 16;
        const unsigned bRow = (lane & 7) + ((lane >> 3) & 1) * 8;
        const unsigned bOff0 = (wd * 4 + (lane >> 4)) * 16;

        for (int ch = 0; ch < 8; ++ch) {
            __syncthreads();
            stage_x(sm, xb, ch, t);
            __syncthreads();
            if (wp < 8) {
#pragma unroll
                for (int kk = 0; kk < 8; ++kk) {
                    const unsigned sg = ch * 128 + kk * 16;
                    const unsigned aA = MT_u + (sg + aRow) * MT_STRIDE;
                    const unsigned bA = XS_u + (kk * 16 + bRow) * XS_STRIDE;
                    unsigned a[8], bq[8];
                    ldsm4t(a[0], a[1], a[2], a[3], aA + aOff0);
                    ldsm4t(a[4], a[5], a[6], a[7], aA + aOff0 + 32);
                    ldsm4t(bq[0], bq[1], bq[2], bq[3], bA + bOff0);
                    ldsm4t(bq[4], bq[5], bq[6], bq[7], bA + bOff0 + 32);
#pragma unroll
                    for (int mi = 0; mi < 2; ++mi)
#pragma unroll
                        for (int ni = 0; ni < 4; ++ni)
                            mma16816(e[mi][ni], a[mi*4], a[mi*4+1], a[mi*4+2],
                                     a[mi*4+3], bq[2*ni], bq[2*ni+1]);
                }
            }
        }
        if (wp < 8) {
#pragma unroll
            for (int mi = 0; mi < 2; ++mi) {
                const int o = wo * 32 + mi * 16 + (lane >> 2);
                float* ob0 = out + ((size_t)(n * 64 + o)) * 512 + m * 128;
                float* ob1 = out + ((size_t)(n * 64 + o + 8)) * 512 + m * 128;
#pragma unroll
                for (int ni = 0; ni < 4; ++ni) {
                    const int db = wd * 32 + ni * 8 + 2 * (lane & 3);
                    float2 v;
                    v.x = e[mi][ni][0]; v.y = e[mi][ni][1]; *(float2*)(ob0 + db) = v;
                    v.x = e[mi][ni][2]; v.y = e[mi][ni][3]; *(float2*)(ob1 + db) = v;
                }
            }
        }
    }
}

// ---------------------------------------------------------------------------
extern "C" void kernel_launch(void* const* d_in, const int* in_sizes, int n_in,
                              void* d_out, int out_size)
{
    const float* x = (const float*)d_in[0];   // [64, 1024, 128] f32
    const float* w = (const float*)d_in[1];   // [4, 64, 128] f32
    float* out = (float*)d_out;               // [64, 64, 512] f32

    cudaFuncSetAttribute(ot_fused_kernel,
                         cudaFuncAttributeMaxDynamicSharedMemorySize, SM_TOTAL);
    ot_fused_kernel<<<256, 1024, SM_TOTAL>>>(x, w, out);
}